// round 2
// baseline (speedup 1.0000x reference)
#include <cuda_runtime.h>
#include <math.h>

#define NJc 50000
#define NSc 50000
#define Ec  1600000
#define DIMc 256
#define D4c  64
#define Lc   2
#define Bc   1024
#define NNEGc 32
#define NEGRc (NNEGc*Bc)
#define WSZc (Lc*DIMc*DIMc)

// ---------------- scratch (device globals; no allocation allowed) ----------------
__device__ float g_Ej[NJc*DIMc];
__device__ float g_Es[NSc*DIMc];
__device__ float g_Gj[NJc*DIMc];
__device__ float g_Gs[NSc*DIMc];
__device__ float g_sEj[NJc*DIMc];
__device__ float g_sEs[NSc*DIMc];
__device__ float g_sGj[NJc*DIMc];
__device__ float g_sGs[NSc*DIMc];
__device__ float g_Tje[NJc*DIMc];
__device__ float g_Tjg[NJc*DIMc];
__device__ float g_Tse[NSc*DIMc];
__device__ float g_Tsg[NSc*DIMc];
__device__ int   g_cnt_j[NJc];
__device__ int   g_cnt_s[NSc];
__device__ int   g_ptr_j[NJc+1];
__device__ int   g_ptr_s[NSc+1];
__device__ int   g_cur_j[NJc];
__device__ int   g_cur_s[NSc];
__device__ int   g_ccol_j[Ec];
__device__ float g_cval_j[Ec];
__device__ int   g_ccol_s[Ec];
__device__ float g_cval_s[Ec];
__device__ float g_gjsel[Bc*DIMc];
__device__ float g_ejsel[Bc*DIMc];
__device__ float g_gssel[Bc*DIMc];
__device__ float g_essel[Bc*DIMc];
__device__ float g_negemb[NEGRc*DIMc];
__device__ float g_sumexp_j[Bc];
__device__ float g_sumexp_s[Bc*NNEGc];
__device__ float g_scalars[8];   // [0]=pos_j sum, [1]=pos_s sum, [2]=wsq

// ---------------- small utility kernels ----------------
__global__ void zero_kernel() {
    int i = blockIdx.x * blockDim.x + threadIdx.x;
    int st = gridDim.x * blockDim.x;
    for (int k = i; k < NJc; k += st) g_cnt_j[k] = 0;
    for (int k = i; k < NSc; k += st) g_cnt_s[k] = 0;
    for (int k = i; k < Bc; k += st) g_sumexp_j[k] = 0.f;
    for (int k = i; k < Bc*NNEGc; k += st) g_sumexp_s[k] = 0.f;
    if (i < 8) g_scalars[i] = 0.f;
}

__global__ void count_kernel(const int* __restrict__ row_j, const int* __restrict__ col_s) {
    int i = blockIdx.x * blockDim.x + threadIdx.x;
    if (i < Ec) {
        atomicAdd(&g_cnt_j[row_j[i]], 1);
        atomicAdd(&g_cnt_s[col_s[i]], 1);
    }
}

// single-block exclusive scan of counts -> ptr (n+1), cur (start cursors)
__global__ void scan_kernel(const int* __restrict__ cnt, int* __restrict__ ptr,
                            int* __restrict__ cur, int n) {
    __shared__ int warp_sums[32];
    __shared__ int s_carry;
    int tid = threadIdx.x;
    if (tid == 0) { s_carry = 0; ptr[0] = 0; }
    __syncthreads();
    for (int base = 0; base < n; base += 1024) {
        int i = base + tid;
        int v = (i < n) ? cnt[i] : 0;
        int inc = v;
        #pragma unroll
        for (int off = 1; off < 32; off <<= 1) {
            int t = __shfl_up_sync(0xffffffffu, inc, off);
            if ((tid & 31) >= off) inc += t;
        }
        if ((tid & 31) == 31) warp_sums[tid >> 5] = inc;
        __syncthreads();
        if (tid < 32) {
            int ws = warp_sums[tid];
            int wi = ws;
            #pragma unroll
            for (int off = 1; off < 32; off <<= 1) {
                int t = __shfl_up_sync(0xffffffffu, wi, off);
                if (tid >= off) wi += t;
            }
            warp_sums[tid] = wi - ws;   // exclusive warp offset
        }
        __syncthreads();
        int excl = inc - v + warp_sums[tid >> 5];
        int carry = s_carry;
        if (i < n) {
            int start = carry + excl;
            cur[i] = start;
            ptr[i + 1] = start + v;
        }
        __syncthreads();
        if (tid == 1023) s_carry = carry + excl + v;
        __syncthreads();
    }
}

__global__ void scatter_kernel(const int* __restrict__ row_j, const int* __restrict__ col_j,
                               const float* __restrict__ val_j,
                               const int* __restrict__ row_s, const int* __restrict__ col_s,
                               const float* __restrict__ val_s) {
    int i = blockIdx.x * blockDim.x + threadIdx.x;
    if (i >= Ec) return;
    int p = atomicAdd(&g_cur_j[row_j[i]], 1);
    g_ccol_j[p] = col_j[i]; g_cval_j[p] = val_j[i];
    int q = atomicAdd(&g_cur_s[col_s[i]], 1);
    g_ccol_s[q] = row_s[i]; g_cval_s[q] = val_s[i];
}

// ---------------- row l2 normalize (warp per row), src may equal dst ----------------
__global__ void l2norm_kernel(const float4* __restrict__ src, float4* __restrict__ dst, int n) {
    int w = (blockIdx.x * blockDim.x + threadIdx.x) >> 5;
    int lane = threadIdx.x & 31;
    if (w >= n) return;
    const float4* s = src + (size_t)w * D4c;
    float4 u0 = s[lane], u1 = s[lane + 32];
    float ss = u0.x*u0.x + u0.y*u0.y + u0.z*u0.z + u0.w*u0.w
             + u1.x*u1.x + u1.y*u1.y + u1.z*u1.z + u1.w*u1.w;
    #pragma unroll
    for (int o = 16; o; o >>= 1) ss += __shfl_xor_sync(0xffffffffu, ss, o);
    float inv = 1.f / fmaxf(sqrtf(ss), 1e-12f);
    float4* d = dst + (size_t)w * D4c;
    d[lane]      = make_float4(u0.x*inv, u0.y*inv, u0.z*inv, u0.w*inv);
    d[lane + 32] = make_float4(u1.x*inv, u1.y*inv, u1.z*inv, u1.w*inv);
}

// ---------------- fused dual SPMM: O1 = A @ X1, O2 = A @ X2 (CSR, warp/row) ----------------
__device__ __forceinline__ void fma4(float4& acc, float v, const float4& u) {
    acc.x = fmaf(v, u.x, acc.x);
    acc.y = fmaf(v, u.y, acc.y);
    acc.z = fmaf(v, u.z, acc.z);
    acc.w = fmaf(v, u.w, acc.w);
}

__global__ __launch_bounds__(256) void spmm_dual_kernel(
    const int* __restrict__ ptr, const int* __restrict__ cols, const float* __restrict__ vals,
    const float4* __restrict__ X1, const float4* __restrict__ X2,
    float4* __restrict__ O1, float4* __restrict__ O2, int n)
{
    int w = (blockIdx.x * blockDim.x + threadIdx.x) >> 5;
    int lane = threadIdx.x & 31;
    if (w >= n) return;
    int s = ptr[w], e = ptr[w + 1];
    float4 z = make_float4(0.f, 0.f, 0.f, 0.f);
    float4 a0 = z, a1 = z, b0 = z, b1 = z;
    int p = s;
    for (; p + 2 <= e; p += 2) {
        int c0 = cols[p], c1 = cols[p + 1];
        float v0 = vals[p], v1 = vals[p + 1];
        const float4* x10 = X1 + (size_t)c0 * D4c;
        const float4* x20 = X2 + (size_t)c0 * D4c;
        const float4* x11 = X1 + (size_t)c1 * D4c;
        const float4* x21 = X2 + (size_t)c1 * D4c;
        float4 p0 = x10[lane], p1 = x10[lane + 32];
        float4 q0 = x20[lane], q1 = x20[lane + 32];
        float4 r0 = x11[lane], r1 = x11[lane + 32];
        float4 t0 = x21[lane], t1 = x21[lane + 32];
        fma4(a0, v0, p0); fma4(a1, v0, p1); fma4(b0, v0, q0); fma4(b1, v0, q1);
        fma4(a0, v1, r0); fma4(a1, v1, r1); fma4(b0, v1, t0); fma4(b1, v1, t1);
    }
    if (p < e) {
        int c0 = cols[p]; float v0 = vals[p];
        const float4* x10 = X1 + (size_t)c0 * D4c;
        const float4* x20 = X2 + (size_t)c0 * D4c;
        float4 p0 = x10[lane], p1 = x10[lane + 32];
        float4 q0 = x20[lane], q1 = x20[lane + 32];
        fma4(a0, v0, p0); fma4(a1, v0, p1); fma4(b0, v0, q0); fma4(b1, v0, q1);
    }
    O1[(size_t)w * D4c + lane] = a0; O1[(size_t)w * D4c + 32 + lane] = a1;
    O2[(size_t)w * D4c + lane] = b0; O2[(size_t)w * D4c + 32 + lane] = b1;
}

// ---------------- SGEMM 128x128x8 (NT: C = A[M,256] * W[N,256]^T) + fused update epilogue ----
// out = old + relu(C); sum = first ? old + out : sum + out
__global__ __launch_bounds__(256) void gemm_update_kernel(
    const float* __restrict__ A, const float* __restrict__ W,
    const float* __restrict__ oldv, float* __restrict__ outv, float* __restrict__ sumv,
    int M, int first)
{
    __shared__ float As[8][128];
    __shared__ float Bs[8][128];
    int tid = threadIdx.x;
    int tx = tid & 15, ty = tid >> 4;
    int rowTile = blockIdx.y * 128;
    int colTile = blockIdx.x * 128;
    float acc[8][8];
    #pragma unroll
    for (int i = 0; i < 8; i++)
        #pragma unroll
        for (int j = 0; j < 8; j++) acc[i][j] = 0.f;

    int lrow = tid >> 1;
    int lquad = (tid & 1) * 4;
    const float* Ag = A + (size_t)(rowTile + lrow) * DIMc + lquad;
    const float* Wg = W + (size_t)(colTile + lrow) * DIMc + lquad;
    bool arow_ok = (rowTile + lrow) < M;

    for (int k0 = 0; k0 < DIMc; k0 += 8) {
        float4 ra = arow_ok ? *(const float4*)(Ag + k0) : make_float4(0.f,0.f,0.f,0.f);
        float4 rb = *(const float4*)(Wg + k0);
        __syncthreads();
        As[lquad+0][lrow] = ra.x; As[lquad+1][lrow] = ra.y;
        As[lquad+2][lrow] = ra.z; As[lquad+3][lrow] = ra.w;
        Bs[lquad+0][lrow] = rb.x; Bs[lquad+1][lrow] = rb.y;
        Bs[lquad+2][lrow] = rb.z; Bs[lquad+3][lrow] = rb.w;
        __syncthreads();
        #pragma unroll
        for (int kk = 0; kk < 8; kk++) {
            float a[8], b[8];
            #pragma unroll
            for (int i = 0; i < 4; i++) {
                a[i]   = As[kk][ty*4 + i];
                a[i+4] = As[kk][ty*4 + i + 64];
                b[i]   = Bs[kk][tx*4 + i];
                b[i+4] = Bs[kk][tx*4 + i + 64];
            }
            #pragma unroll
            for (int i = 0; i < 8; i++)
                #pragma unroll
                for (int j = 0; j < 8; j++)
                    acc[i][j] = fmaf(a[i], b[j], acc[i][j]);
        }
    }
    #pragma unroll
    for (int i = 0; i < 8; i++) {
        int gr = rowTile + ty*4 + (i & 3) + ((i >> 2) * 64);
        if (gr < M) {
            #pragma unroll
            for (int j = 0; j < 8; j++) {
                int gc = colTile + tx*4 + (j & 3) + ((j >> 2) * 64);
                size_t idx = (size_t)gr * DIMc + gc;
                float v = fmaxf(acc[i][j], 0.f);
                float o = oldv[idx];
                float nv = o + v;
                outv[idx] = nv;
                sumv[idx] = first ? (o + nv) : (sumv[idx] + nv);
            }
        }
    }
}

// ---------------- GEMM + exp + per-(row,group) sum (group = 1024 cols) ----------------
__global__ __launch_bounds__(256) void expsum_kernel(
    const float* __restrict__ A, const float* __restrict__ Bm,
    float* __restrict__ sumexp, int ngroups)
{
    __shared__ float As[8][128];
    __shared__ float Bs[8][128];
    __shared__ float red[128];
    int tid = threadIdx.x;
    int tx = tid & 15, ty = tid >> 4;
    int rowTile = blockIdx.y * 128;
    int colTile = blockIdx.x * 128;
    float acc[8][8];
    #pragma unroll
    for (int i = 0; i < 8; i++)
        #pragma unroll
        for (int j = 0; j < 8; j++) acc[i][j] = 0.f;

    int lrow = tid >> 1;
    int lquad = (tid & 1) * 4;
    const float* Ag = A + (size_t)(rowTile + lrow) * DIMc + lquad;
    const float* Bg = Bm + (size_t)(colTile + lrow) * DIMc + lquad;

    for (int k0 = 0; k0 < DIMc; k0 += 8) {
        float4 ra = *(const float4*)(Ag + k0);
        float4 rb = *(const float4*)(Bg + k0);
        __syncthreads();
        As[lquad+0][lrow] = ra.x; As[lquad+1][lrow] = ra.y;
        As[lquad+2][lrow] = ra.z; As[lquad+3][lrow] = ra.w;
        Bs[lquad+0][lrow] = rb.x; Bs[lquad+1][lrow] = rb.y;
        Bs[lquad+2][lrow] = rb.z; Bs[lquad+3][lrow] = rb.w;
        __syncthreads();
        #pragma unroll
        for (int kk = 0; kk < 8; kk++) {
            float a[8], b[8];
            #pragma unroll
            for (int i = 0; i < 4; i++) {
                a[i]   = As[kk][ty*4 + i];
                a[i+4] = As[kk][ty*4 + i + 64];
                b[i]   = Bs[kk][tx*4 + i];
                b[i+4] = Bs[kk][tx*4 + i + 64];
            }
            #pragma unroll
            for (int i = 0; i < 8; i++)
                #pragma unroll
                for (int j = 0; j < 8; j++)
                    acc[i][j] = fmaf(a[i], b[j], acc[i][j]);
        }
    }
    // exp + per-row partial sums
    float rsum[8];
    #pragma unroll
    for (int i = 0; i < 8; i++) {
        rsum[i] = 0.f;
        #pragma unroll
        for (int j = 0; j < 8; j++) rsum[i] += expf(acc[i][j] * 5.0f);  // 1/TEMP = 5
    }
    if (tid < 128) red[tid] = 0.f;
    __syncthreads();
    #pragma unroll
    for (int i = 0; i < 8; i++) {
        int r = ty*4 + (i & 3) + ((i >> 2) * 64);
        atomicAdd(&red[r], rsum[i]);
    }
    __syncthreads();
    if (tid < 128) {
        int gr = rowTile + tid;
        int group = blockIdx.x >> 3;   // 128 cols/tile, 1024 cols/group
        atomicAdd(&sumexp[(size_t)gr * ngroups + group], red[tid]);
    }
}

// ---------------- gathers ----------------
__global__ void gather_kernel(float4* __restrict__ dst, const float4* __restrict__ src,
                              const int* __restrict__ ids) {
    int row = blockIdx.x;
    int id = ids[row];
    dst[(size_t)row * D4c + threadIdx.x] = src[(size_t)id * D4c + threadIdx.x];
}

// ---------------- pos score ----------------
__global__ void pos_kernel() {
    int w = (blockIdx.x * blockDim.x + threadIdx.x) >> 5;
    int lane = threadIdx.x & 31;
    if (w >= Bc) return;
    const float4* gj = (const float4*)g_gjsel + (size_t)w * D4c;
    const float4* ej = (const float4*)g_ejsel + (size_t)w * D4c;
    const float4* gs = (const float4*)g_gssel + (size_t)w * D4c;
    const float4* es = (const float4*)g_essel + (size_t)w * D4c;
    float4 a0 = gj[lane], a1 = gj[lane+32], b0 = ej[lane], b1 = ej[lane+32];
    float4 c0 = gs[lane], c1 = gs[lane+32], d0 = es[lane], d1 = es[lane+32];
    float s1 = a0.x*b0.x + a0.y*b0.y + a0.z*b0.z + a0.w*b0.w
             + a1.x*b1.x + a1.y*b1.y + a1.z*b1.z + a1.w*b1.w;
    float s2 = c0.x*d0.x + c0.y*d0.y + c0.z*d0.z + c0.w*d0.w
             + c1.x*d1.x + c1.y*d1.y + c1.z*d1.z + c1.w*d1.w;
    #pragma unroll
    for (int o = 16; o; o >>= 1) {
        s1 += __shfl_xor_sync(0xffffffffu, s1, o);
        s2 += __shfl_xor_sync(0xffffffffu, s2, o);
    }
    if (lane == 0) {
        float c1v = fminf(fmaxf(s1 * 5.0f, -1.f), 1.f);
        float c2v = fminf(fmaxf(s2 * 5.0f, -1.f), 1.f);
        atomicAdd(&g_scalars[0], c1v);
        atomicAdd(&g_scalars[1], c2v);
    }
}

// ---------------- weight L2 regularizer ----------------
__global__ void wsq_kernel(const float* __restrict__ a, const float* __restrict__ b,
                           const float* __restrict__ c, const float* __restrict__ d) {
    float s = 0.f;
    for (int i = blockIdx.x * blockDim.x + threadIdx.x; i < WSZc; i += gridDim.x * blockDim.x) {
        float x;
        x = a[i]; s += x * x;
        x = b[i]; s += x * x;
        x = c[i]; s += x * x;
        x = d[i]; s += x * x;
    }
    #pragma unroll
    for (int o = 16; o; o >>= 1) s += __shfl_xor_sync(0xffffffffu, s, o);
    __shared__ float sh[8];
    int lane = threadIdx.x & 31, wid = threadIdx.x >> 5;
    if (lane == 0) sh[wid] = s;
    __syncthreads();
    if (threadIdx.x == 0) {
        float t = 0.f;
        for (int i = 0; i < (int)(blockDim.x >> 5); i++) t += sh[i];
        atomicAdd(&g_scalars[2], t);
    }
}

// ---------------- finalize ----------------
__device__ double blk_reduce_1024(double v) {
    __shared__ double sh[32];
    __syncthreads();
    int lane = threadIdx.x & 31, wid = threadIdx.x >> 5;
    #pragma unroll
    for (int o = 16; o; o >>= 1) v += __shfl_down_sync(0xffffffffu, v, o);
    if (lane == 0) sh[wid] = v;
    __syncthreads();
    v = (threadIdx.x < 32) ? sh[threadIdx.x] : 0.0;
    if (wid == 0) {
        #pragma unroll
        for (int o = 16; o; o >>= 1) v += __shfl_down_sync(0xffffffffu, v, o);
    }
    return v;  // valid on thread 0
}

__global__ void finalize_kernel(float* __restrict__ out) {
    int tid = threadIdx.x;
    double a = (tid < Bc) ? log((double)g_sumexp_j[tid] + 1e-8) : 0.0;
    double negj = blk_reduce_1024(a);
    double b = 0.0;
    for (int i = tid; i < Bc * NNEGc; i += 1024)
        b += log((double)g_sumexp_s[i] + 1e-8);
    double negs = blk_reduce_1024(b);
    if (tid == 0) {
        double pos = (double)g_scalars[0] / Bc + (double)g_scalars[1] / Bc;
        double neg = negj / Bc + negs / (double)(Bc * NNEGc);
        double cl = (-pos + neg) * 0.2;
        double reg = 1e-4 * (double)g_scalars[2];
        out[0] = (float)(cl + reg);
        out[1] = (float)cl;
        out[2] = (float)reg;
    }
}

// ---------------- launch ----------------
#define SYM(p, s) do { void* _t = 0; cudaGetSymbolAddress(&_t, s); p = (decltype(p))_t; } while (0)

extern "C" void kernel_launch(void* const* d_in, const int* in_sizes, int n_in,
                              void* d_out, int out_size) {
    (void)in_sizes; (void)n_in; (void)out_size;
    const float* e_j_f   = (const float*)d_in[0];
    const float* e_s_f   = (const float*)d_in[1];
    const float* aug_e_j = (const float*)d_in[2];
    const float* aug_e_s = (const float*)d_in[3];
    const float* val_j   = (const float*)d_in[4];
    const float* val_s   = (const float*)d_in[5];
    const float* W_j     = (const float*)d_in[6];
    const float* W_s     = (const float*)d_in[7];
    const float* W_j_aug = (const float*)d_in[8];
    const float* W_s_aug = (const float*)d_in[9];
    const int* row_j = (const int*)d_in[10];
    const int* col_j = (const int*)d_in[11];
    const int* row_s = (const int*)d_in[12];
    const int* col_s = (const int*)d_in[13];
    const int* j_ids = (const int*)d_in[14];
    const int* s_ids = (const int*)d_in[15];
    const int* negs  = (const int*)d_in[16];
    float* out = (float*)d_out;

    float *Ej, *Es, *Gj, *Gs, *sEj, *sEs, *sGj, *sGs;
    float *Tje, *Tjg, *Tse, *Tsg;
    int *cnt_j, *cnt_s, *ptr_j, *ptr_s, *cur_j, *cur_s, *ccol_j, *ccol_s;
    float *cval_j, *cval_s;
    float *gjsel, *ejsel, *gssel, *essel, *negemb, *sumexp_j, *sumexp_s;
    SYM(Ej, g_Ej); SYM(Es, g_Es); SYM(Gj, g_Gj); SYM(Gs, g_Gs);
    SYM(sEj, g_sEj); SYM(sEs, g_sEs); SYM(sGj, g_sGj); SYM(sGs, g_sGs);
    SYM(Tje, g_Tje); SYM(Tjg, g_Tjg); SYM(Tse, g_Tse); SYM(Tsg, g_Tsg);
    SYM(cnt_j, g_cnt_j); SYM(cnt_s, g_cnt_s);
    SYM(ptr_j, g_ptr_j); SYM(ptr_s, g_ptr_s);
    SYM(cur_j, g_cur_j); SYM(cur_s, g_cur_s);
    SYM(ccol_j, g_ccol_j); SYM(ccol_s, g_ccol_s);
    SYM(cval_j, g_cval_j); SYM(cval_s, g_cval_s);
    SYM(gjsel, g_gjsel); SYM(ejsel, g_ejsel); SYM(gssel, g_gssel); SYM(essel, g_essel);
    SYM(negemb, g_negemb); SYM(sumexp_j, g_sumexp_j); SYM(sumexp_s, g_sumexp_s);

    const int EB = (Ec + 255) / 256;         // 6250
    const int RB = (NJc * 32 + 255) / 256;   // warp-per-row blocks: 6250

    zero_kernel<<<256, 256>>>();
    count_kernel<<<EB, 256>>>(row_j, col_s);
    scan_kernel<<<1, 1024>>>(cnt_j, ptr_j, cur_j, NJc);
    scan_kernel<<<1, 1024>>>(cnt_s, ptr_s, cur_s, NSc);
    scatter_kernel<<<EB, 256>>>(row_j, col_j, val_j, row_s, col_s, val_s);

    l2norm_kernel<<<RB, 256>>>((const float4*)aug_e_j, (float4*)Gj, NJc);
    l2norm_kernel<<<RB, 256>>>((const float4*)aug_e_s, (float4*)Gs, NSc);

    dim3 gemm_grid(2, (NJc + 127) / 128);    // N=256 -> 2 col tiles, 391 row tiles
    for (int l = 0; l < Lc; l++) {
        const float* EjSrc = l ? Ej : e_j_f;
        const float* EsSrc = l ? Es : e_s_f;
        spmm_dual_kernel<<<RB, 256>>>(ptr_j, ccol_j, cval_j,
                                      (const float4*)EsSrc, (const float4*)Gs,
                                      (float4*)Tje, (float4*)Tjg, NJc);
        spmm_dual_kernel<<<RB, 256>>>(ptr_s, ccol_s, cval_s,
                                      (const float4*)EjSrc, (const float4*)Gj,
                                      (float4*)Tse, (float4*)Tsg, NSc);
        gemm_update_kernel<<<gemm_grid, 256>>>(Tje, W_j     + l*DIMc*DIMc, EjSrc, Ej, sEj, NJc, l == 0);
        gemm_update_kernel<<<gemm_grid, 256>>>(Tse, W_s     + l*DIMc*DIMc, EsSrc, Es, sEs, NSc, l == 0);
        gemm_update_kernel<<<gemm_grid, 256>>>(Tjg, W_j_aug + l*DIMc*DIMc, Gj,    Gj, sGj, NJc, l == 0);
        gemm_update_kernel<<<gemm_grid, 256>>>(Tsg, W_s_aug + l*DIMc*DIMc, Gs,    Gs, sGs, NSc, l == 0);
    }

    // final normalize (scale 1/(L+1) cancels in l2norm) — in place
    l2norm_kernel<<<RB, 256>>>((const float4*)sEj, (float4*)sEj, NJc);
    l2norm_kernel<<<RB, 256>>>((const float4*)sEs, (float4*)sEs, NSc);
    l2norm_kernel<<<RB, 256>>>((const float4*)sGj, (float4*)sGj, NJc);
    l2norm_kernel<<<RB, 256>>>((const float4*)sGs, (float4*)sGs, NSc);

    gather_kernel<<<Bc, 64>>>((float4*)gjsel, (const float4*)sGj, j_ids);
    gather_kernel<<<Bc, 64>>>((float4*)ejsel, (const float4*)sEj, j_ids);
    gather_kernel<<<Bc, 64>>>((float4*)gssel, (const float4*)sGs, s_ids);
    gather_kernel<<<Bc, 64>>>((float4*)essel, (const float4*)sEs, s_ids);
    gather_kernel<<<NEGRc, 64>>>((float4*)negemb, (const float4*)sEs, negs);

    dim3 lg(Bc / 128, Bc / 128);             // 8 x 8
    expsum_kernel<<<lg, 256>>>(gjsel, ejsel, sumexp_j, 1);
    dim3 ng(NEGRc / 128, Bc / 128);          // 256 x 8
    expsum_kernel<<<ng, 256>>>(gssel, negemb, sumexp_s, NNEGc);

    pos_kernel<<<Bc / 8, 256>>>();
    wsq_kernel<<<256, 256>>>(W_j, W_s, W_j_aug, W_s_aug);
    finalize_kernel<<<1, 1024>>>(out);
}

// round 3
// speedup vs baseline: 1.0090x; 1.0090x over previous
#include <cuda_runtime.h>
#include <math.h>

#define NJc 50000
#define NSc 50000
#define Ec  1600000
#define DIMc 256
#define D4c  64
#define Lc   2
#define Bc   1024
#define NNEGc 32
#define NEGRc (NNEGc*Bc)
#define WSZc (Lc*DIMc*DIMc)

// ---------------- scratch (device globals; no allocation allowed) ----------------
__device__ float g_Ej[NJc*DIMc];
__device__ float g_Es[NSc*DIMc];
__device__ float g_Gj[NJc*DIMc];
__device__ float g_Gs[NSc*DIMc];
__device__ float g_sEj[NJc*DIMc];
__device__ float g_sEs[NSc*DIMc];
__device__ float g_sGj[NJc*DIMc];
__device__ float g_sGs[NSc*DIMc];
__device__ float g_Tje[NJc*DIMc];
__device__ float g_Tjg[NJc*DIMc];
__device__ float g_Tse[NSc*DIMc];
__device__ float g_Tsg[NSc*DIMc];
__device__ int   g_cnt_j[NJc];
__device__ int   g_cnt_s[NSc];
__device__ int   g_ptr_j[NJc+1];
__device__ int   g_ptr_s[NSc+1];
__device__ int   g_cur_j[NJc];
__device__ int   g_cur_s[NSc];
__device__ int   g_ccol_j[Ec];
__device__ float g_cval_j[Ec];
__device__ int   g_ccol_s[Ec];
__device__ float g_cval_s[Ec];
__device__ float g_gjsel[Bc*DIMc];
__device__ float g_ejsel[Bc*DIMc];
__device__ float g_gssel[Bc*DIMc];
__device__ float g_essel[Bc*DIMc];
__device__ float g_negemb[NEGRc*DIMc];
__device__ float g_sumexp_j[Bc];
__device__ float g_sumexp_s[Bc*NNEGc];
__device__ float g_scalars[8];   // [0]=pos_j sum, [1]=pos_s sum, [2]=wsq

// ---------------- small utility kernels ----------------
__global__ void zero_kernel() {
    int i = blockIdx.x * blockDim.x + threadIdx.x;
    int st = gridDim.x * blockDim.x;
    for (int k = i; k < NJc; k += st) g_cnt_j[k] = 0;
    for (int k = i; k < NSc; k += st) g_cnt_s[k] = 0;
    for (int k = i; k < Bc; k += st) g_sumexp_j[k] = 0.f;
    for (int k = i; k < Bc*NNEGc; k += st) g_sumexp_s[k] = 0.f;
    if (i < 8) g_scalars[i] = 0.f;
}

__global__ void count_kernel(const int* __restrict__ row_j, const int* __restrict__ col_s) {
    int i = blockIdx.x * blockDim.x + threadIdx.x;
    if (i < Ec) {
        atomicAdd(&g_cnt_j[row_j[i]], 1);
        atomicAdd(&g_cnt_s[col_s[i]], 1);
    }
}

// dual single-block exclusive scan: blockIdx.x = 0 -> j arrays, 1 -> s arrays
__global__ void scan2_kernel() {
    const int* cnt = blockIdx.x ? g_cnt_s : g_cnt_j;
    int* ptr = blockIdx.x ? g_ptr_s : g_ptr_j;
    int* cur = blockIdx.x ? g_cur_s : g_cur_j;
    int n = blockIdx.x ? NSc : NJc;
    __shared__ int warp_sums[32];
    __shared__ int s_carry;
    int tid = threadIdx.x;
    if (tid == 0) { s_carry = 0; ptr[0] = 0; }
    __syncthreads();
    for (int base = 0; base < n; base += 1024) {
        int i = base + tid;
        int v = (i < n) ? cnt[i] : 0;
        int inc = v;
        #pragma unroll
        for (int off = 1; off < 32; off <<= 1) {
            int t = __shfl_up_sync(0xffffffffu, inc, off);
            if ((tid & 31) >= off) inc += t;
        }
        if ((tid & 31) == 31) warp_sums[tid >> 5] = inc;
        __syncthreads();
        if (tid < 32) {
            int ws = warp_sums[tid];
            int wi = ws;
            #pragma unroll
            for (int off = 1; off < 32; off <<= 1) {
                int t = __shfl_up_sync(0xffffffffu, wi, off);
                if (tid >= off) wi += t;
            }
            warp_sums[tid] = wi - ws;   // exclusive warp offset
        }
        __syncthreads();
        int excl = inc - v + warp_sums[tid >> 5];
        int carry = s_carry;
        if (i < n) {
            int start = carry + excl;
            cur[i] = start;
            ptr[i + 1] = start + v;
        }
        __syncthreads();
        if (tid == 1023) s_carry = carry + excl + v;
        __syncthreads();
    }
}

__global__ void scatter_kernel(const int* __restrict__ row_j, const int* __restrict__ col_j,
                               const float* __restrict__ val_j,
                               const int* __restrict__ row_s, const int* __restrict__ col_s,
                               const float* __restrict__ val_s) {
    int i = blockIdx.x * blockDim.x + threadIdx.x;
    if (i >= Ec) return;
    int p = atomicAdd(&g_cur_j[row_j[i]], 1);
    g_ccol_j[p] = col_j[i]; g_cval_j[p] = val_j[i];
    int q = atomicAdd(&g_cur_s[col_s[i]], 1);
    g_ccol_s[q] = row_s[i]; g_cval_s[q] = val_s[i];
}

// ---------------- fused row l2 normalize over up to 4 arrays (blockIdx.y selects) ----------
__global__ void l2norm4_kernel(const float4* s0, float4* d0, const float4* s1, float4* d1,
                               const float4* s2, float4* d2, const float4* s3, float4* d3,
                               int n) {
    const float4* src; float4* dst;
    switch (blockIdx.y) {
        case 0: src = s0; dst = d0; break;
        case 1: src = s1; dst = d1; break;
        case 2: src = s2; dst = d2; break;
        default: src = s3; dst = d3; break;
    }
    int w = (blockIdx.x * blockDim.x + threadIdx.x) >> 5;
    int lane = threadIdx.x & 31;
    if (w >= n) return;
    const float4* s = src + (size_t)w * D4c;
    float4 u0 = s[lane], u1 = s[lane + 32];
    float ss = u0.x*u0.x + u0.y*u0.y + u0.z*u0.z + u0.w*u0.w
             + u1.x*u1.x + u1.y*u1.y + u1.z*u1.z + u1.w*u1.w;
    #pragma unroll
    for (int o = 16; o; o >>= 1) ss += __shfl_xor_sync(0xffffffffu, ss, o);
    float inv = 1.f / fmaxf(sqrtf(ss), 1e-12f);
    float4* d = dst + (size_t)w * D4c;
    d[lane]      = make_float4(u0.x*inv, u0.y*inv, u0.z*inv, u0.w*inv);
    d[lane + 32] = make_float4(u1.x*inv, u1.y*inv, u1.z*inv, u1.w*inv);
}

// ---------------- fused dual SPMM: O1 = A @ X1, O2 = A @ X2 (CSR, warp/row) ----------------
__device__ __forceinline__ void fma4(float4& acc, float v, const float4& u) {
    acc.x = fmaf(v, u.x, acc.x);
    acc.y = fmaf(v, u.y, acc.y);
    acc.z = fmaf(v, u.z, acc.z);
    acc.w = fmaf(v, u.w, acc.w);
}

__global__ __launch_bounds__(256) void spmm_dual_kernel(
    const int* __restrict__ ptr, const int* __restrict__ cols, const float* __restrict__ vals,
    const float4* __restrict__ X1, const float4* __restrict__ X2,
    float4* __restrict__ O1, float4* __restrict__ O2, int n)
{
    int w = (blockIdx.x * blockDim.x + threadIdx.x) >> 5;
    int lane = threadIdx.x & 31;
    if (w >= n) return;
    int s = ptr[w], e = ptr[w + 1];
    float4 z = make_float4(0.f, 0.f, 0.f, 0.f);
    float4 a0 = z, a1 = z, b0 = z, b1 = z;
    int p = s;
    for (; p + 2 <= e; p += 2) {
        int c0 = cols[p], c1 = cols[p + 1];
        float v0 = vals[p], v1 = vals[p + 1];
        const float4* x10 = X1 + (size_t)c0 * D4c;
        const float4* x20 = X2 + (size_t)c0 * D4c;
        const float4* x11 = X1 + (size_t)c1 * D4c;
        const float4* x21 = X2 + (size_t)c1 * D4c;
        float4 p0 = x10[lane], p1 = x10[lane + 32];
        float4 q0 = x20[lane], q1 = x20[lane + 32];
        float4 r0 = x11[lane], r1 = x11[lane + 32];
        float4 t0 = x21[lane], t1 = x21[lane + 32];
        fma4(a0, v0, p0); fma4(a1, v0, p1); fma4(b0, v0, q0); fma4(b1, v0, q1);
        fma4(a0, v1, r0); fma4(a1, v1, r1); fma4(b0, v1, t0); fma4(b1, v1, t1);
    }
    if (p < e) {
        int c0 = cols[p]; float v0 = vals[p];
        const float4* x10 = X1 + (size_t)c0 * D4c;
        const float4* x20 = X2 + (size_t)c0 * D4c;
        float4 p0 = x10[lane], p1 = x10[lane + 32];
        float4 q0 = x20[lane], q1 = x20[lane + 32];
        fma4(a0, v0, p0); fma4(a1, v0, p1); fma4(b0, v0, q0); fma4(b1, v0, q1);
    }
    O1[(size_t)w * D4c + lane] = a0; O1[(size_t)w * D4c + 32 + lane] = a1;
    O2[(size_t)w * D4c + lane] = b0; O2[(size_t)w * D4c + 32 + lane] = b1;
}

// ---------------- double-buffered SGEMM 128x128x16 (NT) + fused update epilogue ----------
// out = old + relu(C); sum = first ? old + out : sum + out
__global__ __launch_bounds__(256) void gemm_update_kernel(
    const float* __restrict__ A, const float* __restrict__ W,
    const float* __restrict__ oldv, float* __restrict__ outv, float* __restrict__ sumv,
    int M, int first)
{
    __shared__ float As[2][16][128];
    __shared__ float Bs[2][16][128];
    int tid = threadIdx.x;
    int tx = tid & 15, ty = tid >> 4;
    int rowTile = blockIdx.y * 128;
    int colTile = blockIdx.x * 128;
    float acc[8][8];
    #pragma unroll
    for (int i = 0; i < 8; i++)
        #pragma unroll
        for (int j = 0; j < 8; j++) acc[i][j] = 0.f;

    int lrow = tid & 127;            // 0..127 (warp-consecutive -> conflict-free STS)
    int khalf = (tid >> 7) * 8;      // 0 or 8
    const float* Ag = A + (size_t)(rowTile + lrow) * DIMc + khalf;
    const float* Wg = W + (size_t)(colTile + lrow) * DIMc + khalf;
    bool arow_ok = (rowTile + lrow) < M;
    const float4 z4 = make_float4(0.f, 0.f, 0.f, 0.f);

    float4 ra0 = arow_ok ? *(const float4*)(Ag + 0) : z4;
    float4 ra1 = arow_ok ? *(const float4*)(Ag + 4) : z4;
    float4 rb0 = *(const float4*)(Wg + 0);
    float4 rb1 = *(const float4*)(Wg + 4);
    As[0][khalf+0][lrow] = ra0.x; As[0][khalf+1][lrow] = ra0.y;
    As[0][khalf+2][lrow] = ra0.z; As[0][khalf+3][lrow] = ra0.w;
    As[0][khalf+4][lrow] = ra1.x; As[0][khalf+5][lrow] = ra1.y;
    As[0][khalf+6][lrow] = ra1.z; As[0][khalf+7][lrow] = ra1.w;
    Bs[0][khalf+0][lrow] = rb0.x; Bs[0][khalf+1][lrow] = rb0.y;
    Bs[0][khalf+2][lrow] = rb0.z; Bs[0][khalf+3][lrow] = rb0.w;
    Bs[0][khalf+4][lrow] = rb1.x; Bs[0][khalf+5][lrow] = rb1.y;
    Bs[0][khalf+6][lrow] = rb1.z; Bs[0][khalf+7][lrow] = rb1.w;
    __syncthreads();

    int buf = 0;
    for (int k0 = 16; k0 <= DIMc; k0 += 16) {
        bool more = k0 < DIMc;
        if (more) {
            ra0 = arow_ok ? *(const float4*)(Ag + k0) : z4;
            ra1 = arow_ok ? *(const float4*)(Ag + k0 + 4) : z4;
            rb0 = *(const float4*)(Wg + k0);
            rb1 = *(const float4*)(Wg + k0 + 4);
        }
        #pragma unroll
        for (int kk = 0; kk < 16; kk++) {
            float a[8], b[8];
            #pragma unroll
            for (int i = 0; i < 4; i++) {
                a[i]   = As[buf][kk][ty*4 + i];
                a[i+4] = As[buf][kk][ty*4 + i + 64];
                b[i]   = Bs[buf][kk][tx*4 + i];
                b[i+4] = Bs[buf][kk][tx*4 + i + 64];
            }
            #pragma unroll
            for (int i = 0; i < 8; i++)
                #pragma unroll
                for (int j = 0; j < 8; j++)
                    acc[i][j] = fmaf(a[i], b[j], acc[i][j]);
        }
        if (more) {
            int nb = buf ^ 1;
            As[nb][khalf+0][lrow] = ra0.x; As[nb][khalf+1][lrow] = ra0.y;
            As[nb][khalf+2][lrow] = ra0.z; As[nb][khalf+3][lrow] = ra0.w;
            As[nb][khalf+4][lrow] = ra1.x; As[nb][khalf+5][lrow] = ra1.y;
            As[nb][khalf+6][lrow] = ra1.z; As[nb][khalf+7][lrow] = ra1.w;
            Bs[nb][khalf+0][lrow] = rb0.x; Bs[nb][khalf+1][lrow] = rb0.y;
            Bs[nb][khalf+2][lrow] = rb0.z; Bs[nb][khalf+3][lrow] = rb0.w;
            Bs[nb][khalf+4][lrow] = rb1.x; Bs[nb][khalf+5][lrow] = rb1.y;
            Bs[nb][khalf+6][lrow] = rb1.z; Bs[nb][khalf+7][lrow] = rb1.w;
            __syncthreads();
            buf = nb;
        }
    }
    #pragma unroll
    for (int i = 0; i < 8; i++) {
        int gr = rowTile + ty*4 + (i & 3) + ((i >> 2) * 64);
        if (gr < M) {
            #pragma unroll
            for (int j = 0; j < 8; j++) {
                int gc = colTile + tx*4 + (j & 3) + ((j >> 2) * 64);
                size_t idx = (size_t)gr * DIMc + gc;
                float v = fmaxf(acc[i][j], 0.f);
                float o = oldv[idx];
                float nv = o + v;
                outv[idx] = nv;
                sumv[idx] = first ? (o + nv) : (sumv[idx] + nv);
            }
        }
    }
}

// ---------------- double-buffered GEMM + exp + per-(row,group) sum ----------------
__global__ __launch_bounds__(256) void expsum_kernel(
    const float* __restrict__ A, const float* __restrict__ Bm,
    float* __restrict__ sumexp, int ngroups)
{
    __shared__ float As[2][16][128];
    __shared__ float Bs[2][16][128];
    __shared__ float red[128];
    int tid = threadIdx.x;
    int tx = tid & 15, ty = tid >> 4;
    int rowTile = blockIdx.y * 128;
    int colTile = blockIdx.x * 128;
    float acc[8][8];
    #pragma unroll
    for (int i = 0; i < 8; i++)
        #pragma unroll
        for (int j = 0; j < 8; j++) acc[i][j] = 0.f;

    int lrow = tid & 127;
    int khalf = (tid >> 7) * 8;
    const float* Ag = A + (size_t)(rowTile + lrow) * DIMc + khalf;
    const float* Bg = Bm + (size_t)(colTile + lrow) * DIMc + khalf;

    float4 ra0 = *(const float4*)(Ag + 0);
    float4 ra1 = *(const float4*)(Ag + 4);
    float4 rb0 = *(const float4*)(Bg + 0);
    float4 rb1 = *(const float4*)(Bg + 4);
    As[0][khalf+0][lrow] = ra0.x; As[0][khalf+1][lrow] = ra0.y;
    As[0][khalf+2][lrow] = ra0.z; As[0][khalf+3][lrow] = ra0.w;
    As[0][khalf+4][lrow] = ra1.x; As[0][khalf+5][lrow] = ra1.y;
    As[0][khalf+6][lrow] = ra1.z; As[0][khalf+7][lrow] = ra1.w;
    Bs[0][khalf+0][lrow] = rb0.x; Bs[0][khalf+1][lrow] = rb0.y;
    Bs[0][khalf+2][lrow] = rb0.z; Bs[0][khalf+3][lrow] = rb0.w;
    Bs[0][khalf+4][lrow] = rb1.x; Bs[0][khalf+5][lrow] = rb1.y;
    Bs[0][khalf+6][lrow] = rb1.z; Bs[0][khalf+7][lrow] = rb1.w;
    __syncthreads();

    int buf = 0;
    for (int k0 = 16; k0 <= DIMc; k0 += 16) {
        bool more = k0 < DIMc;
        if (more) {
            ra0 = *(const float4*)(Ag + k0);
            ra1 = *(const float4*)(Ag + k0 + 4);
            rb0 = *(const float4*)(Bg + k0);
            rb1 = *(const float4*)(Bg + k0 + 4);
        }
        #pragma unroll
        for (int kk = 0; kk < 16; kk++) {
            float a[8], b[8];
            #pragma unroll
            for (int i = 0; i < 4; i++) {
                a[i]   = As[buf][kk][ty*4 + i];
                a[i+4] = As[buf][kk][ty*4 + i + 64];
                b[i]   = Bs[buf][kk][tx*4 + i];
                b[i+4] = Bs[buf][kk][tx*4 + i + 64];
            }
            #pragma unroll
            for (int i = 0; i < 8; i++)
                #pragma unroll
                for (int j = 0; j < 8; j++)
                    acc[i][j] = fmaf(a[i], b[j], acc[i][j]);
        }
        if (more) {
            int nb = buf ^ 1;
            As[nb][khalf+0][lrow] = ra0.x; As[nb][khalf+1][lrow] = ra0.y;
            As[nb][khalf+2][lrow] = ra0.z; As[nb][khalf+3][lrow] = ra0.w;
            As[nb][khalf+4][lrow] = ra1.x; As[nb][khalf+5][lrow] = ra1.y;
            As[nb][khalf+6][lrow] = ra1.z; As[nb][khalf+7][lrow] = ra1.w;
            Bs[nb][khalf+0][lrow] = rb0.x; Bs[nb][khalf+1][lrow] = rb0.y;
            Bs[nb][khalf+2][lrow] = rb0.z; Bs[nb][khalf+3][lrow] = rb0.w;
            Bs[nb][khalf+4][lrow] = rb1.x; Bs[nb][khalf+5][lrow] = rb1.y;
            Bs[nb][khalf+6][lrow] = rb1.z; Bs[nb][khalf+7][lrow] = rb1.w;
            __syncthreads();
            buf = nb;
        }
    }
    // exp + per-row partial sums
    float rsum[8];
    #pragma unroll
    for (int i = 0; i < 8; i++) {
        rsum[i] = 0.f;
        #pragma unroll
        for (int j = 0; j < 8; j++) rsum[i] += expf(acc[i][j] * 5.0f);  // 1/TEMP = 5
    }
    if (tid < 128) red[tid] = 0.f;
    __syncthreads();
    #pragma unroll
    for (int i = 0; i < 8; i++) {
        int r = ty*4 + (i & 3) + ((i >> 2) * 64);
        atomicAdd(&red[r], rsum[i]);
    }
    __syncthreads();
    if (tid < 128) {
        int gr = rowTile + tid;
        int group = blockIdx.x >> 3;   // 128 cols/tile, 1024 cols/group
        atomicAdd(&sumexp[(size_t)gr * ngroups + group], red[tid]);
    }
}

// ---------------- gathers (blockIdx.y selects one of 4 dst/src pairs) ----------------
__global__ void gather4_kernel(const int* __restrict__ j_ids, const int* __restrict__ s_ids) {
    float4* dst; const float4* src; const int* ids;
    switch (blockIdx.y) {
        case 0: dst = (float4*)g_gjsel; src = (const float4*)g_sGj; ids = j_ids; break;
        case 1: dst = (float4*)g_ejsel; src = (const float4*)g_sEj; ids = j_ids; break;
        case 2: dst = (float4*)g_gssel; src = (const float4*)g_sGs; ids = s_ids; break;
        default: dst = (float4*)g_essel; src = (const float4*)g_sEs; ids = s_ids; break;
    }
    int row = blockIdx.x;
    int id = ids[row];
    dst[(size_t)row * D4c + threadIdx.x] = src[(size_t)id * D4c + threadIdx.x];
}

__global__ void gather_kernel(float4* __restrict__ dst, const float4* __restrict__ src,
                              const int* __restrict__ ids) {
    int row = blockIdx.x;
    int id = ids[row];
    dst[(size_t)row * D4c + threadIdx.x] = src[(size_t)id * D4c + threadIdx.x];
}

// ---------------- pos score ----------------
__global__ void pos_kernel() {
    int w = (blockIdx.x * blockDim.x + threadIdx.x) >> 5;
    int lane = threadIdx.x & 31;
    if (w >= Bc) return;
    const float4* gj = (const float4*)g_gjsel + (size_t)w * D4c;
    const float4* ej = (const float4*)g_ejsel + (size_t)w * D4c;
    const float4* gs = (const float4*)g_gssel + (size_t)w * D4c;
    const float4* es = (const float4*)g_essel + (size_t)w * D4c;
    float4 a0 = gj[lane], a1 = gj[lane+32], b0 = ej[lane], b1 = ej[lane+32];
    float4 c0 = gs[lane], c1 = gs[lane+32], d0 = es[lane], d1 = es[lane+32];
    float s1 = a0.x*b0.x + a0.y*b0.y + a0.z*b0.z + a0.w*b0.w
             + a1.x*b1.x + a1.y*b1.y + a1.z*b1.z + a1.w*b1.w;
    float s2 = c0.x*d0.x + c0.y*d0.y + c0.z*d0.z + c0.w*d0.w
             + c1.x*d1.x + c1.y*d1.y + c1.z*d1.z + c1.w*d1.w;
    #pragma unroll
    for (int o = 16; o; o >>= 1) {
        s1 += __shfl_xor_sync(0xffffffffu, s1, o);
        s2 += __shfl_xor_sync(0xffffffffu, s2, o);
    }
    if (lane == 0) {
        float c1v = fminf(fmaxf(s1 * 5.0f, -1.f), 1.f);
        float c2v = fminf(fmaxf(s2 * 5.0f, -1.f), 1.f);
        atomicAdd(&g_scalars[0], c1v);
        atomicAdd(&g_scalars[1], c2v);
    }
}

// ---------------- weight L2 regularizer ----------------
__global__ void wsq_kernel(const float* __restrict__ a, const float* __restrict__ b,
                           const float* __restrict__ c, const float* __restrict__ d) {
    float s = 0.f;
    for (int i = blockIdx.x * blockDim.x + threadIdx.x; i < WSZc; i += gridDim.x * blockDim.x) {
        float x;
        x = a[i]; s += x * x;
        x = b[i]; s += x * x;
        x = c[i]; s += x * x;
        x = d[i]; s += x * x;
    }
    #pragma unroll
    for (int o = 16; o; o >>= 1) s += __shfl_xor_sync(0xffffffffu, s, o);
    __shared__ float sh[8];
    int lane = threadIdx.x & 31, wid = threadIdx.x >> 5;
    if (lane == 0) sh[wid] = s;
    __syncthreads();
    if (threadIdx.x == 0) {
        float t = 0.f;
        for (int i = 0; i < (int)(blockDim.x >> 5); i++) t += sh[i];
        atomicAdd(&g_scalars[2], t);
    }
}

// ---------------- finalize ----------------
__device__ double blk_reduce_1024(double v) {
    __shared__ double sh[32];
    __syncthreads();
    int lane = threadIdx.x & 31, wid = threadIdx.x >> 5;
    #pragma unroll
    for (int o = 16; o; o >>= 1) v += __shfl_down_sync(0xffffffffu, v, o);
    if (lane == 0) sh[wid] = v;
    __syncthreads();
    v = (threadIdx.x < 32) ? sh[threadIdx.x] : 0.0;
    if (wid == 0) {
        #pragma unroll
        for (int o = 16; o; o >>= 1) v += __shfl_down_sync(0xffffffffu, v, o);
    }
    return v;  // valid on thread 0
}

__global__ void finalize_kernel(float* __restrict__ out) {
    int tid = threadIdx.x;
    double a = (tid < Bc) ? log((double)g_sumexp_j[tid] + 1e-8) : 0.0;
    double negj = blk_reduce_1024(a);
    double b = 0.0;
    for (int i = tid; i < Bc * NNEGc; i += 1024)
        b += log((double)g_sumexp_s[i] + 1e-8);
    double negs = blk_reduce_1024(b);
    if (tid == 0) {
        double pos = (double)g_scalars[0] / Bc + (double)g_scalars[1] / Bc;
        double neg = negj / Bc + negs / (double)(Bc * NNEGc);
        double cl = (-pos + neg) * 0.2;
        double reg = 1e-4 * (double)g_scalars[2];
        out[0] = (float)(cl + reg);
        out[1] = (float)cl;
        out[2] = (float)reg;
    }
}

// ---------------- launch ----------------
#define SYM(p, s) do { void* _t = 0; cudaGetSymbolAddress(&_t, s); p = (decltype(p))_t; } while (0)

extern "C" void kernel_launch(void* const* d_in, const int* in_sizes, int n_in,
                              void* d_out, int out_size) {
    (void)in_sizes; (void)n_in; (void)out_size;
    const float* e_j_f   = (const float*)d_in[0];
    const float* e_s_f   = (const float*)d_in[1];
    const float* aug_e_j = (const float*)d_in[2];
    const float* aug_e_s = (const float*)d_in[3];
    const float* val_j   = (const float*)d_in[4];
    const float* val_s   = (const float*)d_in[5];
    const float* W_j     = (const float*)d_in[6];
    const float* W_s     = (const float*)d_in[7];
    const float* W_j_aug = (const float*)d_in[8];
    const float* W_s_aug = (const float*)d_in[9];
    const int* row_j = (const int*)d_in[10];
    const int* col_j = (const int*)d_in[11];
    const int* row_s = (const int*)d_in[12];
    const int* col_s = (const int*)d_in[13];
    const int* j_ids = (const int*)d_in[14];
    const int* s_ids = (const int*)d_in[15];
    const int* negs  = (const int*)d_in[16];
    float* out = (float*)d_out;

    float *Ej, *Es, *Gj, *Gs, *sEj, *sEs, *sGj, *sGs;
    float *Tje, *Tjg, *Tse, *Tsg;
    int *ptr_j, *ptr_s, *ccol_j, *ccol_s;
    float *cval_j, *cval_s;
    float *gjsel, *ejsel, *gssel, *essel, *negemb, *sumexp_j, *sumexp_s;
    SYM(Ej, g_Ej); SYM(Es, g_Es); SYM(Gj, g_Gj); SYM(Gs, g_Gs);
    SYM(sEj, g_sEj); SYM(sEs, g_sEs); SYM(sGj, g_sGj); SYM(sGs, g_sGs);
    SYM(Tje, g_Tje); SYM(Tjg, g_Tjg); SYM(Tse, g_Tse); SYM(Tsg, g_Tsg);
    SYM(ptr_j, g_ptr_j); SYM(ptr_s, g_ptr_s);
    SYM(ccol_j, g_ccol_j); SYM(ccol_s, g_ccol_s);
    SYM(cval_j, g_cval_j); SYM(cval_s, g_cval_s);
    SYM(gjsel, g_gjsel); SYM(ejsel, g_ejsel); SYM(gssel, g_gssel); SYM(essel, g_essel);
    SYM(negemb, g_negemb); SYM(sumexp_j, g_sumexp_j); SYM(sumexp_s, g_sumexp_s);

    const int EB = (Ec + 255) / 256;         // 6250
    const int RB = (NJc * 32 + 255) / 256;   // warp-per-row blocks: 6250

    zero_kernel<<<256, 256>>>();
    count_kernel<<<EB, 256>>>(row_j, col_s);
    scan2_kernel<<<2, 1024>>>();
    scatter_kernel<<<EB, 256>>>(row_j, col_j, val_j, row_s, col_s, val_s);

    {   // initial l2norm of aug embeddings (2 arrays in one launch)
        dim3 g(RB, 2);
        l2norm4_kernel<<<g, 256>>>((const float4*)aug_e_j, (float4*)Gj,
                                   (const float4*)aug_e_s, (float4*)Gs,
                                   (const float4*)aug_e_j, (float4*)Gj,
                                   (const float4*)aug_e_s, (float4*)Gs, NJc);
    }

    dim3 gemm_grid(2, (NJc + 127) / 128);    // N=256 -> 2 col tiles, 391 row tiles
    for (int l = 0; l < Lc; l++) {
        const float* EjSrc = l ? Ej : e_j_f;
        const float* EsSrc = l ? Es : e_s_f;
        spmm_dual_kernel<<<RB, 256>>>(ptr_j, ccol_j, cval_j,
                                      (const float4*)EsSrc, (const float4*)Gs,
                                      (float4*)Tje, (float4*)Tjg, NJc);
        spmm_dual_kernel<<<RB, 256>>>(ptr_s, ccol_s, cval_s,
                                      (const float4*)EjSrc, (const float4*)Gj,
                                      (float4*)Tse, (float4*)Tsg, NSc);
        gemm_update_kernel<<<gemm_grid, 256>>>(Tje, W_j     + l*DIMc*DIMc, EjSrc, Ej, sEj, NJc, l == 0);
        gemm_update_kernel<<<gemm_grid, 256>>>(Tse, W_s     + l*DIMc*DIMc, EsSrc, Es, sEs, NSc, l == 0);
        gemm_update_kernel<<<gemm_grid, 256>>>(Tjg, W_j_aug + l*DIMc*DIMc, Gj,    Gj, sGj, NJc, l == 0);
        gemm_update_kernel<<<gemm_grid, 256>>>(Tsg, W_s_aug + l*DIMc*DIMc, Gs,    Gs, sGs, NSc, l == 0);
    }

    {   // final normalize (scale 1/(L+1) cancels in l2norm) — in place, 4 arrays one launch
        dim3 g(RB, 4);
        l2norm4_kernel<<<g, 256>>>((const float4*)sEj, (float4*)sEj,
                                   (const float4*)sEs, (float4*)sEs,
                                   (const float4*)sGj, (float4*)sGj,
                                   (const float4*)sGs, (float4*)sGs, NJc);
    }

    {
        dim3 g(Bc, 4);
        gather4_kernel<<<g, 64>>>(j_ids, s_ids);
    }
    gather_kernel<<<NEGRc, 64>>>((float4*)negemb, (const float4*)sEs, negs);

    dim3 lg(Bc / 128, Bc / 128);             // 8 x 8
    expsum_kernel<<<lg, 256>>>(gjsel, ejsel, sumexp_j, 1);
    dim3 ng(NEGRc / 128, Bc / 128);          // 256 x 8
    expsum_kernel<<<ng, 256>>>(gssel, negemb, sumexp_s, NNEGc);

    pos_kernel<<<Bc / 8, 256>>>();
    wsq_kernel<<<256, 256>>>(W_j, W_s, W_j_aug, W_s_aug);
    finalize_kernel<<<1, 1024>>>(out);
}